// round 2
// baseline (speedup 1.0000x reference)
#include <cuda_runtime.h>

#define DIM 128
#define VMAX 50000
#define CMAX 150000
#define EPMAX 200000
#define ENMAX 200000
#define NITER 4

// ---------------- static device scratch (no allocations allowed) ----------------
__device__ int   g_pv[EPMAX];
__device__ int   g_pc[EPMAX];
__device__ int   g_nv[ENMAX];
__device__ int   g_nc[ENMAX];
__device__ float g_pinv[EPMAX];
__device__ float g_ninv[ENMAX];
__device__ int   g_cnt[2 * VMAX + 2 * CMAX];
// msg layout: [mv_p (V*128) | mv_n (V*128) | mc_p (C*128) | mc_n (C*128)]
__device__ float g_msg[(size_t)(2 * VMAX + 2 * CMAX) * DIM];
// agg layout: [vagg_p | vagg_n | cagg_p | cagg_n]
__device__ float g_agg[(size_t)(2 * VMAX + 2 * CMAX) * DIM];

// ---------------- utility kernels ----------------
__global__ void zero_f4(float4* __restrict__ p, int n4) {
    int i = blockIdx.x * blockDim.x + threadIdx.x;
    if (i < n4) p[i] = make_float4(0.f, 0.f, 0.f, 0.f);
}

__global__ void count_kernel(const int* __restrict__ eidx,
                             const int* __restrict__ vI, const int* __restrict__ cI,
                             int ne,
                             int* __restrict__ vcnt, int* __restrict__ ccnt,
                             int* __restrict__ ev, int* __restrict__ ec) {
    int e = blockIdx.x * blockDim.x + threadIdx.x;
    if (e >= ne) return;
    int ed = eidx[e];
    int v = vI[ed];
    int c = cI[ed];
    ev[e] = v;
    ec[e] = c;
    atomicAdd(vcnt + v, 1);
    atomicAdd(ccnt + c, 1);
}

__global__ void inv_kernel(const int* __restrict__ ev, const int* __restrict__ ec,
                           const int* __restrict__ vcnt, const int* __restrict__ ccnt,
                           int ne, float* __restrict__ inv) {
    int e = blockIdx.x * blockDim.x + threadIdx.x;
    if (e >= ne) return;
    int dv = max(vcnt[ev[e]], 1);
    int dc = max(ccnt[ec[e]], 1);
    inv[e] = 1.0f / (sqrtf((float)dv) * sqrtf((float)dc));
}

// ---------------- fused 2-layer MLP: Y = relu(X@W1+b1)@W2+b2 ----------------
// tile: 64 rows x 128 cols, 128 threads, each thread 8x8 micro-tile.
// smem: Xs[64][129] + Hs[64][129] (dynamic, 66 KB). Weights stream through L1.
__global__ __launch_bounds__(128) void mlp2_kernel(
    const float* __restrict__ X, int N,
    const float* __restrict__ W1, const float* __restrict__ b1,
    const float* __restrict__ W2, const float* __restrict__ b2,
    float* __restrict__ Y) {
    extern __shared__ float smem[];
    float (*Xs)[129] = (float(*)[129])smem;
    float (*Hs)[129] = (float(*)[129])(smem + 64 * 129);

    const int tid = threadIdx.x;
    const int rg = tid >> 4;         // 0..7  (8 rows each)
    const int cg = tid & 15;         // 0..15 (8 cols each)
    const int r0 = rg * 8;
    const int c0 = cg * 8;
    const int rowbase = blockIdx.x * 64;

    // load X tile (zero-pad past N)
    for (int i = tid; i < 64 * 32; i += 128) {
        int r = i >> 5;
        int q = (i & 31) * 4;
        float4 v = make_float4(0.f, 0.f, 0.f, 0.f);
        int row = rowbase + r;
        if (row < N) v = *reinterpret_cast<const float4*>(X + (size_t)row * DIM + q);
        Xs[r][q + 0] = v.x; Xs[r][q + 1] = v.y; Xs[r][q + 2] = v.z; Xs[r][q + 3] = v.w;
    }
    __syncthreads();

    float acc[8][8];
    // ---- stage 1: H = relu(X@W1 + b1) ----
#pragma unroll
    for (int j = 0; j < 8; j++) {
        float bv = b1[c0 + j];
#pragma unroll
        for (int i = 0; i < 8; i++) acc[i][j] = bv;
    }
#pragma unroll 2
    for (int k = 0; k < DIM; k++) {
        float a[8];
#pragma unroll
        for (int i = 0; i < 8; i++) a[i] = Xs[r0 + i][k];
        float4 w0 = *reinterpret_cast<const float4*>(W1 + k * DIM + c0);
        float4 w1 = *reinterpret_cast<const float4*>(W1 + k * DIM + c0 + 4);
        float w[8] = {w0.x, w0.y, w0.z, w0.w, w1.x, w1.y, w1.z, w1.w};
#pragma unroll
        for (int i = 0; i < 8; i++)
#pragma unroll
            for (int j = 0; j < 8; j++)
                acc[i][j] = fmaf(a[i], w[j], acc[i][j]);
    }
#pragma unroll
    for (int i = 0; i < 8; i++)
#pragma unroll
        for (int j = 0; j < 8; j++)
            Hs[r0 + i][c0 + j] = fmaxf(acc[i][j], 0.f);
    __syncthreads();

    // ---- stage 2: Y = H@W2 + b2 ----
#pragma unroll
    for (int j = 0; j < 8; j++) {
        float bv = b2[c0 + j];
#pragma unroll
        for (int i = 0; i < 8; i++) acc[i][j] = bv;
    }
#pragma unroll 2
    for (int k = 0; k < DIM; k++) {
        float a[8];
#pragma unroll
        for (int i = 0; i < 8; i++) a[i] = Hs[r0 + i][k];
        float4 w0 = *reinterpret_cast<const float4*>(W2 + k * DIM + c0);
        float4 w1 = *reinterpret_cast<const float4*>(W2 + k * DIM + c0 + 4);
        float w[8] = {w0.x, w0.y, w0.z, w0.w, w1.x, w1.y, w1.z, w1.w};
#pragma unroll
        for (int i = 0; i < 8; i++)
#pragma unroll
            for (int j = 0; j < 8; j++)
                acc[i][j] = fmaf(a[i], w[j], acc[i][j]);
    }
#pragma unroll
    for (int i = 0; i < 8; i++) {
        int row = rowbase + r0 + i;
        if (row < N) {
            float* yp = Y + (size_t)row * DIM + c0;
            *reinterpret_cast<float4*>(yp) = make_float4(acc[i][0], acc[i][1], acc[i][2], acc[i][3]);
            *reinterpret_cast<float4*>(yp + 4) = make_float4(acc[i][4], acc[i][5], acc[i][6], acc[i][7]);
        }
    }
}

// ---------------- update GEMM: Y = [X0|X1|X2] @ W(384x128) + b ----------------
__global__ __launch_bounds__(128) void upd_kernel(
    const float* __restrict__ X0, const float* __restrict__ X1, const float* __restrict__ X2,
    int N, const float* __restrict__ W, const float* __restrict__ b,
    float* __restrict__ Y) {
    __shared__ float Xs[64][129];
    const int tid = threadIdx.x;
    const int rg = tid >> 4;
    const int cg = tid & 15;
    const int r0 = rg * 8;
    const int c0 = cg * 8;
    const int rowbase = blockIdx.x * 64;

    float acc[8][8];
#pragma unroll
    for (int j = 0; j < 8; j++) {
        float bv = b[c0 + j];
#pragma unroll
        for (int i = 0; i < 8; i++) acc[i][j] = bv;
    }

    for (int s = 0; s < 3; s++) {
        const float* Xp = (s == 0) ? X0 : ((s == 1) ? X1 : X2);
        __syncthreads();
        for (int i = tid; i < 64 * 32; i += 128) {
            int r = i >> 5;
            int q = (i & 31) * 4;
            float4 v = make_float4(0.f, 0.f, 0.f, 0.f);
            int row = rowbase + r;
            if (row < N) v = *reinterpret_cast<const float4*>(Xp + (size_t)row * DIM + q);
            Xs[r][q + 0] = v.x; Xs[r][q + 1] = v.y; Xs[r][q + 2] = v.z; Xs[r][q + 3] = v.w;
        }
        __syncthreads();
        const float* Wseg = W + (size_t)s * DIM * DIM;
#pragma unroll 2
        for (int k = 0; k < DIM; k++) {
            float a[8];
#pragma unroll
            for (int i = 0; i < 8; i++) a[i] = Xs[r0 + i][k];
            float4 w0 = *reinterpret_cast<const float4*>(Wseg + k * DIM + c0);
            float4 w1 = *reinterpret_cast<const float4*>(Wseg + k * DIM + c0 + 4);
            float w[8] = {w0.x, w0.y, w0.z, w0.w, w1.x, w1.y, w1.z, w1.w};
#pragma unroll
            for (int i = 0; i < 8; i++)
#pragma unroll
                for (int j = 0; j < 8; j++)
                    acc[i][j] = fmaf(a[i], w[j], acc[i][j]);
        }
    }

#pragma unroll
    for (int i = 0; i < 8; i++) {
        int row = rowbase + r0 + i;
        if (row < N) {
            float* yp = Y + (size_t)row * DIM + c0;
            *reinterpret_cast<float4*>(yp) = make_float4(acc[i][0], acc[i][1], acc[i][2], acc[i][3]);
            *reinterpret_cast<float4*>(yp + 4) = make_float4(acc[i][4], acc[i][5], acc[i][6], acc[i][7]);
        }
    }
}

// ---------------- edge scatter: both directions, one pass ----------------
// thread = (edge, float4-chunk). atomicAdd w/ unused result -> REDG (no return).
__global__ void scatter_kernel(const int* __restrict__ ev, const int* __restrict__ ec,
                               const float* __restrict__ inv, int ne,
                               const float* __restrict__ msg_v, const float* __restrict__ msg_c,
                               float* __restrict__ agg_c, float* __restrict__ agg_v) {
    int idx = blockIdx.x * blockDim.x + threadIdx.x;
    if (idx >= ne * 32) return;
    int e = idx >> 5;
    int j = (idx & 31) * 4;
    int v = ev[e];
    int c = ec[e];
    float s = inv[e];

    float4 mv = *reinterpret_cast<const float4*>(msg_v + (size_t)v * DIM + j);
    float* dc = agg_c + (size_t)c * DIM + j;
    atomicAdd(dc + 0, mv.x * s);
    atomicAdd(dc + 1, mv.y * s);
    atomicAdd(dc + 2, mv.z * s);
    atomicAdd(dc + 3, mv.w * s);

    float4 mc = *reinterpret_cast<const float4*>(msg_c + (size_t)c * DIM + j);
    float* dv = agg_v + (size_t)v * DIM + j;
    atomicAdd(dv + 0, mc.x * s);
    atomicAdd(dv + 1, mc.y * s);
    atomicAdd(dv + 2, mc.z * s);
    atomicAdd(dv + 3, mc.w * s);
}

// ---------------- host launcher ----------------
extern "C" void kernel_launch(void* const* d_in, const int* in_sizes, int n_in,
                              void* d_out, int out_size) {
    // v_size / c_size scalars may or may not be present as inputs
    int base = (in_sizes[0] == 1 && in_sizes[1] == 1) ? 2 : 0;
    const int*   v_edge = (const int*)d_in[base + 0];
    const int*   c_edge = (const int*)d_in[base + 1];
    const int*   p_idx  = (const int*)d_in[base + 2];
    const int*   n_idx  = (const int*)d_in[base + 3];
    const float* v_emb  = (const float*)d_in[base + 4];
    const float* c_emb  = (const float*)d_in[base + 5];
    const float* W1     = (const float*)d_in[base + 6];
    const float* b1     = (const float*)d_in[base + 7];
    const float* W2     = (const float*)d_in[base + 8];
    const float* b2     = (const float*)d_in[base + 9];
    const float* cW     = (const float*)d_in[base + 10];
    const float* cb     = (const float*)d_in[base + 11];
    const float* vW     = (const float*)d_in[base + 12];
    const float* vbias  = (const float*)d_in[base + 13];

    const int EP = in_sizes[base + 2];
    const int EN = in_sizes[base + 3];
    const int V  = in_sizes[base + 4] / DIM;
    const int C  = in_sizes[base + 5] / DIM;

    // resolve scratch symbol addresses
    int *pv, *pc, *nv, *nc, *cnt;
    float *pinv, *ninv, *msg, *agg;
    cudaGetSymbolAddress((void**)&pv,   g_pv);
    cudaGetSymbolAddress((void**)&pc,   g_pc);
    cudaGetSymbolAddress((void**)&nv,   g_nv);
    cudaGetSymbolAddress((void**)&nc,   g_nc);
    cudaGetSymbolAddress((void**)&pinv, g_pinv);
    cudaGetSymbolAddress((void**)&ninv, g_ninv);
    cudaGetSymbolAddress((void**)&cnt,  g_cnt);
    cudaGetSymbolAddress((void**)&msg,  g_msg);
    cudaGetSymbolAddress((void**)&agg,  g_agg);

    int*   vcnt_p = cnt;
    int*   vcnt_n = cnt + VMAX;
    int*   ccnt_p = cnt + 2 * VMAX;
    int*   ccnt_n = cnt + 2 * VMAX + CMAX;
    float* mv_p = msg;
    float* mv_n = msg + (size_t)VMAX * DIM;
    float* mc_p = msg + (size_t)2 * VMAX * DIM;
    float* mc_n = msg + ((size_t)2 * VMAX + CMAX) * DIM;
    float* vagg_p = agg;
    float* vagg_n = agg + (size_t)VMAX * DIM;
    float* cagg_p = agg + (size_t)2 * VMAX * DIM;
    float* cagg_n = agg + ((size_t)2 * VMAX + CMAX) * DIM;

    const int MLP_SMEM = 2 * 64 * 129 * (int)sizeof(float);  // 66048 B
    cudaFuncSetAttribute(mlp2_kernel, cudaFuncAttributeMaxDynamicSharedMemorySize, MLP_SMEM);

    // degrees + per-edge endpoints + inverse norms (input-only, recomputed each call)
    {
        int cntN4 = (2 * VMAX + 2 * CMAX) / 4;
        zero_f4<<<(cntN4 + 255) / 256, 256>>>((float4*)cnt, cntN4);
    }
    count_kernel<<<(EP + 255) / 256, 256>>>(p_idx, v_edge, c_edge, EP, vcnt_p, ccnt_p, pv, pc);
    count_kernel<<<(EN + 255) / 256, 256>>>(n_idx, v_edge, c_edge, EN, vcnt_n, ccnt_n, nv, nc);
    inv_kernel<<<(EP + 255) / 256, 256>>>(pv, pc, vcnt_p, ccnt_p, EP, pinv);
    inv_kernel<<<(EN + 255) / 256, 256>>>(nv, nc, vcnt_n, ccnt_n, EN, ninv);

    // output slab doubles as the embedding history: [5,V,128] then [5,C,128]
    float* out   = (float*)d_out;
    float* out_v = out;
    float* out_c = out + (size_t)(NITER + 1) * V * DIM;
    cudaMemcpyAsync(out_v, v_emb, (size_t)V * DIM * sizeof(float), cudaMemcpyDeviceToDevice);
    cudaMemcpyAsync(out_c, c_emb, (size_t)C * DIM * sizeof(float), cudaMemcpyDeviceToDevice);

    const int vblocks = (V + 63) / 64;
    const int cblocks = (C + 63) / 64;
    const size_t aggN4 = (size_t)(2 * VMAX + 2 * CMAX) * DIM / 4;

    for (int t = 0; t < NITER; t++) {
        const float* vt = out_v + (size_t)t * V * DIM;
        const float* ct = out_c + (size_t)t * C * DIM;

        // 4 message MLPs (node-level)
        mlp2_kernel<<<vblocks, 128, MLP_SMEM>>>(vt, V, W1 + 0 * DIM * DIM, b1 + 0 * DIM,
                                                W2 + 0 * DIM * DIM, b2 + 0 * DIM, mv_p);
        mlp2_kernel<<<vblocks, 128, MLP_SMEM>>>(vt, V, W1 + 1 * DIM * DIM, b1 + 1 * DIM,
                                                W2 + 1 * DIM * DIM, b2 + 1 * DIM, mv_n);
        mlp2_kernel<<<cblocks, 128, MLP_SMEM>>>(ct, C, W1 + 2 * DIM * DIM, b1 + 2 * DIM,
                                                W2 + 2 * DIM * DIM, b2 + 2 * DIM, mc_p);
        mlp2_kernel<<<cblocks, 128, MLP_SMEM>>>(ct, C, W1 + 3 * DIM * DIM, b1 + 3 * DIM,
                                                W2 + 3 * DIM * DIM, b2 + 3 * DIM, mc_n);

        // zero aggregates, then scatter both polarities (both directions per edge)
        zero_f4<<<(int)((aggN4 + 255) / 256), 256>>>((float4*)agg, (int)aggN4);
        scatter_kernel<<<(EP * 32 + 255) / 256, 256>>>(pv, pc, pinv, EP, mv_p, mc_p, cagg_p, vagg_p);
        scatter_kernel<<<(EN * 32 + 255) / 256, 256>>>(nv, nc, ninv, EN, mv_n, mc_n, cagg_n, vagg_n);

        // node updates (concat GEMM, K=384)
        upd_kernel<<<cblocks, 128>>>(ct, cagg_p, cagg_n, C, cW, cb,
                                     out_c + (size_t)(t + 1) * C * DIM);
        upd_kernel<<<vblocks, 128>>>(vt, vagg_p, vagg_n, V, vW, vbias,
                                     out_v + (size_t)(t + 1) * V * DIM);
    }
}

// round 3
// speedup vs baseline: 1.2003x; 1.2003x over previous
#include <cuda_runtime.h>

#define DIM 128
#define VMAX 50000
#define CMAX 150000
#define EPMAX 200000
#define ENMAX 200000
#define NITER 4

typedef unsigned long long u64;

// ---------------- static device scratch (no allocations allowed) ----------------
__device__ int   g_pv[EPMAX];
__device__ int   g_pc[EPMAX];
__device__ int   g_nv[ENMAX];
__device__ int   g_nc[ENMAX];
__device__ float g_pinv[EPMAX];
__device__ float g_ninv[ENMAX];
__device__ int   g_cnt[2 * VMAX + 2 * CMAX];
// msg layout: [mv_p (V*128) | mv_n (V*128) | mc_p (C*128) | mc_n (C*128)]
__device__ float g_msg[(size_t)(2 * VMAX + 2 * CMAX) * DIM];
// agg layout: [vagg_p | vagg_n | cagg_p | cagg_n]
__device__ float g_agg[(size_t)(2 * VMAX + 2 * CMAX) * DIM];

// ---------------- f32x2 packed-FMA helpers (Blackwell-only, ptxas won't emit) ----
__device__ __forceinline__ u64 fma2(u64 a, u64 b, u64 c) {
    u64 d; asm("fma.rn.f32x2 %0, %1, %2, %3;" : "=l"(d) : "l"(a), "l"(b), "l"(c)); return d;
}
__device__ __forceinline__ u64 pack2(float x) {
    u64 d; asm("mov.b64 %0, {%1, %2};" : "=l"(d) : "f"(x), "f"(x)); return d;
}
__device__ __forceinline__ float2 unpack2(u64 d) {
    float2 r; asm("mov.b64 {%0, %1}, %2;" : "=f"(r.x), "=f"(r.y) : "l"(d)); return r;
}

// ---------------- utility kernels ----------------
__global__ void count_kernel(const int* __restrict__ eidx,
                             const int* __restrict__ vI, const int* __restrict__ cI,
                             int ne,
                             int* __restrict__ vcnt, int* __restrict__ ccnt,
                             int* __restrict__ ev, int* __restrict__ ec) {
    int e = blockIdx.x * blockDim.x + threadIdx.x;
    if (e >= ne) return;
    int ed = eidx[e];
    int v = vI[ed];
    int c = cI[ed];
    ev[e] = v;
    ec[e] = c;
    atomicAdd(vcnt + v, 1);
    atomicAdd(ccnt + c, 1);
}

__global__ void inv_kernel(const int* __restrict__ ev, const int* __restrict__ ec,
                           const int* __restrict__ vcnt, const int* __restrict__ ccnt,
                           int ne, float* __restrict__ inv) {
    int e = blockIdx.x * blockDim.x + threadIdx.x;
    if (e >= ne) return;
    int dv = max(vcnt[ev[e]], 1);
    int dc = max(ccnt[ec[e]], 1);
    inv[e] = 1.0f / (sqrtf((float)dv) * sqrtf((float)dc));
}

// ---------------- shared GEMM building blocks ----------------
// tile: 64 rows x 128 cols, 128 threads, each thread 8x8 micro-tile (as 8x4 f32x2).
__device__ __forceinline__ void load_tile(float (*S)[129], const float* __restrict__ X,
                                          int rowbase, int N, int tid) {
    for (int i = tid; i < 64 * 32; i += 128) {
        int r = i >> 5;
        int q = (i & 31) * 4;
        float4 v = make_float4(0.f, 0.f, 0.f, 0.f);
        int row = rowbase + r;
        if (row < N) v = *reinterpret_cast<const float4*>(X + (size_t)row * DIM + q);
        S[r][q + 0] = v.x; S[r][q + 1] = v.y; S[r][q + 2] = v.z; S[r][q + 3] = v.w;
    }
}

__device__ __forceinline__ void acc_init(u64 acc[8][4], const float* __restrict__ b, int c0) {
    const u64* bp = reinterpret_cast<const u64*>(b + c0);  // c0*4 is 32B-aligned
#pragma unroll
    for (int j = 0; j < 4; j++) {
        u64 bv = bp[j];
#pragma unroll
        for (int i = 0; i < 8; i++) acc[i][j] = bv;
    }
}

__device__ __forceinline__ void gemm_acc(const float (*S)[129], const float* __restrict__ W,
                                         u64 acc[8][4], int r0, int c0) {
#pragma unroll 2
    for (int k = 0; k < DIM; k++) {
        u64 a[8];
#pragma unroll
        for (int i = 0; i < 8; i++) a[i] = pack2(S[r0 + i][k]);
        ulonglong2 wa = *reinterpret_cast<const ulonglong2*>(W + k * DIM + c0);
        ulonglong2 wb = *reinterpret_cast<const ulonglong2*>(W + k * DIM + c0 + 4);
        u64 w[4] = {wa.x, wa.y, wb.x, wb.y};
#pragma unroll
        for (int i = 0; i < 8; i++)
#pragma unroll
            for (int j = 0; j < 4; j++)
                acc[i][j] = fma2(a[i], w[j], acc[i][j]);
    }
}

// ---------------- fused 4-MLP kernel: all 4 message MLPs in one grid ----------------
// segments: 0 = p_v2c(V), 1 = n_v2c(V), 2 = p_c2v(C), 3 = n_c2v(C)
__global__ __launch_bounds__(128) void mlp4_kernel(
    const float* __restrict__ vt, const float* __restrict__ ct, int V, int C,
    const float* __restrict__ W1, const float* __restrict__ b1,
    const float* __restrict__ W2, const float* __restrict__ b2,
    int vblocks, int cblocks) {
    __shared__ float S[64][129];

    int bx = blockIdx.x;
    int seg, local;
    if (bx < vblocks)                { seg = 0; local = bx; }
    else if (bx < 2 * vblocks)       { seg = 1; local = bx - vblocks; }
    else if (bx < 2 * vblocks + cblocks) { seg = 2; local = bx - 2 * vblocks; }
    else                             { seg = 3; local = bx - 2 * vblocks - cblocks; }

    const float* X = (seg < 2) ? vt : ct;
    const int N = (seg < 2) ? V : C;
    float* Y = g_msg + ((seg == 0) ? (size_t)0
                 : (seg == 1) ? (size_t)VMAX * DIM
                 : (seg == 2) ? (size_t)2 * VMAX * DIM
                              : ((size_t)2 * VMAX + CMAX) * DIM);
    const float* w1 = W1 + (size_t)seg * DIM * DIM;
    const float* w2 = W2 + (size_t)seg * DIM * DIM;
    const float* bb1 = b1 + seg * DIM;
    const float* bb2 = b2 + seg * DIM;

    const int tid = threadIdx.x;
    const int r0 = (tid >> 4) * 8;
    const int c0 = (tid & 15) * 8;
    const int rowbase = local * 64;

    load_tile(S, X, rowbase, N, tid);
    __syncthreads();

    u64 acc[8][4];
    // stage 1: H = relu(X@W1 + b1)
    acc_init(acc, bb1, c0);
    gemm_acc(S, w1, acc, r0, c0);
    __syncthreads();   // all reads of X-tile done; reuse S for H
#pragma unroll
    for (int i = 0; i < 8; i++)
#pragma unroll
        for (int j = 0; j < 4; j++) {
            float2 f = unpack2(acc[i][j]);
            S[r0 + i][c0 + 2 * j + 0] = fmaxf(f.x, 0.f);
            S[r0 + i][c0 + 2 * j + 1] = fmaxf(f.y, 0.f);
        }
    __syncthreads();

    // stage 2: Y = H@W2 + b2
    acc_init(acc, bb2, c0);
    gemm_acc(S, w2, acc, r0, c0);
#pragma unroll
    for (int i = 0; i < 8; i++) {
        int row = rowbase + r0 + i;
        if (row < N) {
            float2 f0 = unpack2(acc[i][0]);
            float2 f1 = unpack2(acc[i][1]);
            float2 f2 = unpack2(acc[i][2]);
            float2 f3 = unpack2(acc[i][3]);
            float* yp = Y + (size_t)row * DIM + c0;
            *reinterpret_cast<float4*>(yp)     = make_float4(f0.x, f0.y, f1.x, f1.y);
            *reinterpret_cast<float4*>(yp + 4) = make_float4(f2.x, f2.y, f3.x, f3.y);
        }
    }
}

// ---------------- update GEMM: Y = [X0|X1|X2] @ W(384x128) + b ----------------
__global__ __launch_bounds__(128) void upd_kernel(
    const float* __restrict__ X0, const float* __restrict__ X1, const float* __restrict__ X2,
    int N, const float* __restrict__ W, const float* __restrict__ b,
    float* __restrict__ Y) {
    __shared__ float S[64][129];
    const int tid = threadIdx.x;
    const int r0 = (tid >> 4) * 8;
    const int c0 = (tid & 15) * 8;
    const int rowbase = blockIdx.x * 64;

    u64 acc[8][4];
    acc_init(acc, b, c0);

    for (int s = 0; s < 3; s++) {
        const float* Xp = (s == 0) ? X0 : ((s == 1) ? X1 : X2);
        __syncthreads();
        load_tile(S, Xp, rowbase, N, tid);
        __syncthreads();
        gemm_acc(S, W + (size_t)s * DIM * DIM, acc, r0, c0);
    }

#pragma unroll
    for (int i = 0; i < 8; i++) {
        int row = rowbase + r0 + i;
        if (row < N) {
            float2 f0 = unpack2(acc[i][0]);
            float2 f1 = unpack2(acc[i][1]);
            float2 f2 = unpack2(acc[i][2]);
            float2 f3 = unpack2(acc[i][3]);
            float* yp = Y + (size_t)row * DIM + c0;
            *reinterpret_cast<float4*>(yp)     = make_float4(f0.x, f0.y, f1.x, f1.y);
            *reinterpret_cast<float4*>(yp + 4) = make_float4(f2.x, f2.y, f3.x, f3.y);
        }
    }
}

// ---------------- edge scatter: both directions, one pass, v4 reductions --------
__global__ void scatter_kernel(const int* __restrict__ ev, const int* __restrict__ ec,
                               const float* __restrict__ inv, int ne,
                               const float* __restrict__ msg_v, const float* __restrict__ msg_c,
                               float* __restrict__ agg_c, float* __restrict__ agg_v) {
    int idx = blockIdx.x * blockDim.x + threadIdx.x;
    if (idx >= ne * 32) return;
    int e = idx >> 5;
    int j = (idx & 31) * 4;
    int v = ev[e];
    int c = ec[e];
    float s = inv[e];

    float4 mv = *reinterpret_cast<const float4*>(msg_v + (size_t)v * DIM + j);
    float* dc = agg_c + (size_t)c * DIM + j;
    asm volatile("red.global.add.v4.f32 [%0], {%1, %2, %3, %4};"
                 :: "l"(dc), "f"(mv.x * s), "f"(mv.y * s), "f"(mv.z * s), "f"(mv.w * s)
                 : "memory");

    float4 mc = *reinterpret_cast<const float4*>(msg_c + (size_t)c * DIM + j);
    float* dv = agg_v + (size_t)v * DIM + j;
    asm volatile("red.global.add.v4.f32 [%0], {%1, %2, %3, %4};"
                 :: "l"(dv), "f"(mc.x * s), "f"(mc.y * s), "f"(mc.z * s), "f"(mc.w * s)
                 : "memory");
}

// ---------------- host launcher ----------------
extern "C" void kernel_launch(void* const* d_in, const int* in_sizes, int n_in,
                              void* d_out, int out_size) {
    // v_size / c_size scalars may or may not be present as inputs
    int base = (in_sizes[0] == 1 && in_sizes[1] == 1) ? 2 : 0;
    const int*   v_edge = (const int*)d_in[base + 0];
    const int*   c_edge = (const int*)d_in[base + 1];
    const int*   p_idx  = (const int*)d_in[base + 2];
    const int*   n_idx  = (const int*)d_in[base + 3];
    const float* v_emb  = (const float*)d_in[base + 4];
    const float* c_emb  = (const float*)d_in[base + 5];
    const float* W1     = (const float*)d_in[base + 6];
    const float* b1     = (const float*)d_in[base + 7];
    const float* W2     = (const float*)d_in[base + 8];
    const float* b2     = (const float*)d_in[base + 9];
    const float* cW     = (const float*)d_in[base + 10];
    const float* cb     = (const float*)d_in[base + 11];
    const float* vW     = (const float*)d_in[base + 12];
    const float* vbias  = (const float*)d_in[base + 13];

    const int EP = in_sizes[base + 2];
    const int EN = in_sizes[base + 3];
    const int V  = in_sizes[base + 4] / DIM;
    const int C  = in_sizes[base + 5] / DIM;

    int *pv, *pc, *nv, *nc, *cnt;
    float *pinv, *ninv, *msg, *agg;
    cudaGetSymbolAddress((void**)&pv,   g_pv);
    cudaGetSymbolAddress((void**)&pc,   g_pc);
    cudaGetSymbolAddress((void**)&nv,   g_nv);
    cudaGetSymbolAddress((void**)&nc,   g_nc);
    cudaGetSymbolAddress((void**)&pinv, g_pinv);
    cudaGetSymbolAddress((void**)&ninv, g_ninv);
    cudaGetSymbolAddress((void**)&cnt,  g_cnt);
    cudaGetSymbolAddress((void**)&msg,  g_msg);
    cudaGetSymbolAddress((void**)&agg,  g_agg);

    int* vcnt_p = cnt;
    int* vcnt_n = cnt + VMAX;
    int* ccnt_p = cnt + 2 * VMAX;
    int* ccnt_n = cnt + 2 * VMAX + CMAX;
    float* mv_p = msg;
    float* mv_n = msg + (size_t)VMAX * DIM;
    float* mc_p = msg + (size_t)2 * VMAX * DIM;
    float* mc_n = msg + ((size_t)2 * VMAX + CMAX) * DIM;
    float* vagg_p = agg;
    float* vagg_n = agg + (size_t)VMAX * DIM;
    float* cagg_p = agg + (size_t)2 * VMAX * DIM;
    float* cagg_n = agg + ((size_t)2 * VMAX + CMAX) * DIM;

    // degrees + per-edge endpoints + inverse norms
    cudaMemsetAsync(cnt, 0, (size_t)(2 * VMAX + 2 * CMAX) * sizeof(int));
    count_kernel<<<(EP + 255) / 256, 256>>>(p_idx, v_edge, c_edge, EP, vcnt_p, ccnt_p, pv, pc);
    count_kernel<<<(EN + 255) / 256, 256>>>(n_idx, v_edge, c_edge, EN, vcnt_n, ccnt_n, nv, nc);
    inv_kernel<<<(EP + 255) / 256, 256>>>(pv, pc, vcnt_p, ccnt_p, EP, pinv);
    inv_kernel<<<(EN + 255) / 256, 256>>>(nv, nc, vcnt_n, ccnt_n, EN, ninv);

    // output slab doubles as the embedding history: [5,V,128] then [5,C,128]
    float* out   = (float*)d_out;
    float* out_v = out;
    float* out_c = out + (size_t)(NITER + 1) * V * DIM;
    cudaMemcpyAsync(out_v, v_emb, (size_t)V * DIM * sizeof(float), cudaMemcpyDeviceToDevice);
    cudaMemcpyAsync(out_c, c_emb, (size_t)C * DIM * sizeof(float), cudaMemcpyDeviceToDevice);

    const int vblocks = (V + 63) / 64;
    const int cblocks = (C + 63) / 64;
    const int totblocks = 2 * vblocks + 2 * cblocks;
    const size_t aggBytes = (size_t)(2 * VMAX + 2 * CMAX) * DIM * sizeof(float);

    for (int t = 0; t < NITER; t++) {
        const float* vt = out_v + (size_t)t * V * DIM;
        const float* ct = out_c + (size_t)t * C * DIM;

        // all 4 message MLPs in one launch
        mlp4_kernel<<<totblocks, 128>>>(vt, ct, V, C, W1, b1, W2, b2, vblocks, cblocks);

        // zero aggregates, then scatter both polarities (both directions per edge)
        cudaMemsetAsync(agg, 0, aggBytes);
        scatter_kernel<<<(EP * 32 + 255) / 256, 256>>>(pv, pc, pinv, EP, mv_p, mc_p, cagg_p, vagg_p);
        scatter_kernel<<<(EN * 32 + 255) / 256, 256>>>(nv, nc, ninv, EN, mv_n, mc_n, cagg_n, vagg_n);

        // node updates (concat GEMM, K=384)
        upd_kernel<<<cblocks, 128>>>(ct, cagg_p, cagg_n, C, cW, cb,
                                     out_c + (size_t)(t + 1) * C * DIM);
        upd_kernel<<<vblocks, 128>>>(vt, vagg_p, vagg_n, V, vW, vbias,
                                     out_v + (size_t)(t + 1) * V * DIM);
    }
}

// round 10
// speedup vs baseline: 2.3566x; 1.9633x over previous
#include <cuda_runtime.h>
#include <cuda_bf16.h>
#include <cstdint>

#define DIM 128
#define VMAX 50000
#define CMAX 150000
#define EPMAX 200000
#define ENMAX 200000
#define NITER 4

// ---------------- static device scratch (no allocations allowed) ----------------
__device__ int   g_pv[EPMAX];
__device__ int   g_pc[EPMAX];
__device__ int   g_nv[ENMAX];
__device__ int   g_nc[ENMAX];
__device__ float g_pinv[EPMAX];
__device__ float g_ninv[ENMAX];
__device__ int   g_cnt[2 * VMAX + 2 * CMAX];
// msg layout: [mv_p (V*128) | mv_n (V*128) | mc_p (C*128) | mc_n (C*128)]
__device__ float g_msg[(size_t)(2 * VMAX + 2 * CMAX) * DIM];
// agg layout: [vagg_p | vagg_n | cagg_p | cagg_n]
__device__ float g_agg[(size_t)(2 * VMAX + 2 * CMAX) * DIM];
// pre-split bf16 weight images, B-operand layout [N][K], blocked 8x8 atoms.
// slots: 0-3 W1[seg], 4-7 W2[seg], 8-10 cW parts, 11-13 vW parts. per slot: hi 32KB then lo 32KB.
__device__ unsigned char g_wb[14 * 65536];

// ---------------- helpers ----------------
__device__ __forceinline__ uint32_t smem_u32(const void* p) {
    uint32_t a;
    asm("{ .reg .u64 t; cvta.to.shared.u64 t, %1; cvt.u32.u64 %0, t; }" : "=r"(a) : "l"(p));
    return a;
}

// blocked 8x8 bf16 atom layout for a [128][128] tile: atom = 8 rows x 8 cols = 128B contiguous.
__device__ __forceinline__ uint32_t a_off(int row, int col) {
    return (uint32_t)(((row >> 3) * 16 + (col >> 3)) * 128 + (row & 7) * 16 + (col & 7) * 2);
}

__device__ __forceinline__ void ldsm4(uint32_t* r, uint32_t addr) {
    asm volatile("ldmatrix.sync.aligned.m8n8.x4.shared.b16 {%0,%1,%2,%3}, [%4];"
                 : "=r"(r[0]), "=r"(r[1]), "=r"(r[2]), "=r"(r[3]) : "r"(addr));
}

__device__ __forceinline__ void mma16816(float* c, const uint32_t* a, const uint32_t* b) {
    asm volatile(
        "mma.sync.aligned.m16n8k16.row.col.f32.bf16.bf16.f32 "
        "{%0,%1,%2,%3}, {%4,%5,%6,%7}, {%8,%9}, {%0,%1,%2,%3};"
        : "+f"(c[0]), "+f"(c[1]), "+f"(c[2]), "+f"(c[3])
        : "r"(a[0]), "r"(a[1]), "r"(a[2]), "r"(a[3]), "r"(b[0]), "r"(b[1]));
}

__device__ __forceinline__ uint32_t pack_hi(float x0, float x1, float& r0, float& r1) {
    __nv_bfloat16 h0 = __float2bfloat16(x0), h1 = __float2bfloat16(x1);
    r0 = x0 - __bfloat162float(h0);
    r1 = x1 - __bfloat162float(h1);
    return (uint32_t)__bfloat16_as_ushort(h0) | ((uint32_t)__bfloat16_as_ushort(h1) << 16);
}
__device__ __forceinline__ uint32_t pack_lo(float r0, float r1) {
    __nv_bfloat16 l0 = __float2bfloat16(r0), l1 = __float2bfloat16(r1);
    return (uint32_t)__bfloat16_as_ushort(l0) | ((uint32_t)__bfloat16_as_ushort(l1) << 16);
}

// smem byte offsets: A hi | A lo | B hi | B lo  (each 32KB)
#define SM_AHI 0
#define SM_ALO 32768
#define SM_BHI 65536
#define SM_BLO 98304
#define SM_BYTES 131072

// load 128-row X tile (fp32 global) -> split bf16 hi/lo into blocked smem A planes
__device__ __forceinline__ void load_A(char* smem, const float* __restrict__ X,
                                       int rowbase, int N, int tid, int nthr) {
    for (int i = tid; i < 128 * 32; i += nthr) {
        int row = i >> 5;
        int cg = (i & 31) * 4;
        float4 x = make_float4(0.f, 0.f, 0.f, 0.f);
        int grow = rowbase + row;
        if (grow < N) x = *reinterpret_cast<const float4*>(X + (size_t)grow * DIM + cg);
        float rx, ry, rz, rw;
        uint32_t h01 = pack_hi(x.x, x.y, rx, ry);
        uint32_t h23 = pack_hi(x.z, x.w, rz, rw);
        uint32_t l01 = pack_lo(rx, ry);
        uint32_t l23 = pack_lo(rz, rw);
        uint32_t o = a_off(row, cg);   // cg % 8 in {0,4} -> 8B aligned
        *reinterpret_cast<uint2*>(smem + SM_AHI + o) = make_uint2(h01, h23);
        *reinterpret_cast<uint2*>(smem + SM_ALO + o) = make_uint2(l01, l23);
    }
}

// copy one pre-built 64KB weight image (hi 32KB + lo 32KB) into smem B planes
__device__ __forceinline__ void load_B(char* smem, int slot, int tid, int nthr) {
    const float4* src = reinterpret_cast<const float4*>(g_wb + (size_t)slot * 65536);
    float4* dst = reinterpret_cast<float4*>(smem + SM_BHI);
    for (int i = tid; i < 4096; i += nthr) dst[i] = src[i];
}

// 128x128x128 GEMM, 3-term bf16 split, accumulate into acc[16][4] (warp = 16 rows).
__device__ __forceinline__ void gemm3(uint32_t sA, uint32_t sAlo, uint32_t sB, uint32_t sBlo,
                                      float acc[16][4], int lid, int mr) {
    const int j = lid >> 3, lr = lid & 7;
    const uint32_t ac = (uint32_t)(((mr >> 3) + (j & 1)) * 16 + (j >> 1)) * 128 + lr * 16;
    const uint32_t bc = (uint32_t)((j >> 1) * 16 + (j & 1)) * 128 + lr * 16;
#pragma unroll
    for (int ks = 0; ks < 8; ks++) {
        uint32_t ah[4], al[4];
        ldsm4(ah, sA + ac + ks * 256);
        ldsm4(al, sAlo + ac + ks * 256);
#pragma unroll
        for (int p = 0; p < 8; p++) {
            uint32_t bh[4], bl[4];
            ldsm4(bh, sB + bc + p * 4096 + ks * 256);
            ldsm4(bl, sBlo + bc + p * 4096 + ks * 256);
            mma16816(acc[2 * p],     ah, bh);
            mma16816(acc[2 * p + 1], ah, bh + 2);
            mma16816(acc[2 * p],     al, bh);
            mma16816(acc[2 * p + 1], al, bh + 2);
            mma16816(acc[2 * p],     ah, bl);
            mma16816(acc[2 * p + 1], ah, bl + 2);
        }
    }
}

// ---------------- weight prep: split + transpose + block, once per launch ----------------
__global__ void prep_kernel(const float* __restrict__ W1, const float* __restrict__ W2,
                            const float* __restrict__ cW, const float* __restrict__ vW) {
    int idx = blockIdx.x * blockDim.x + threadIdx.x;
    if (idx >= 14 * 16384) return;
    int slot = idx >> 14;
    int e = idx & 16383;
    int n = e >> 7;     // B row (output col)
    int k = e & 127;    // B col (reduction)
    float w;
    if (slot < 4)       w = W1[(size_t)slot * 16384 + k * 128 + n];
    else if (slot < 8)  w = W2[(size_t)(slot - 4) * 16384 + k * 128 + n];
    else if (slot < 11) w = cW[(size_t)((slot - 8) * 128 + k) * 128 + n];
    else                w = vW[(size_t)((slot - 11) * 128 + k) * 128 + n];
    __nv_bfloat16 h = __float2bfloat16(w);
    __nv_bfloat16 l = __float2bfloat16(w - __bfloat162float(h));
    unsigned char* base = g_wb + (size_t)slot * 65536;
    uint32_t o = a_off(n, k);
    *reinterpret_cast<__nv_bfloat16*>(base + o) = h;
    *reinterpret_cast<__nv_bfloat16*>(base + 32768 + o) = l;
}

// ---------------- utility kernels ----------------
__global__ void count_kernel(const int* __restrict__ eidx,
                             const int* __restrict__ vI, const int* __restrict__ cI,
                             int ne, int* __restrict__ vcnt, int* __restrict__ ccnt,
                             int* __restrict__ ev, int* __restrict__ ec) {
    int e = blockIdx.x * blockDim.x + threadIdx.x;
    if (e >= ne) return;
    int ed = eidx[e];
    int v = vI[ed];
    int c = cI[ed];
    ev[e] = v; ec[e] = c;
    atomicAdd(vcnt + v, 1);
    atomicAdd(ccnt + c, 1);
}

__global__ void inv_kernel(const int* __restrict__ ev, const int* __restrict__ ec,
                           const int* __restrict__ vcnt, const int* __restrict__ ccnt,
                           int ne, float* __restrict__ inv) {
    int e = blockIdx.x * blockDim.x + threadIdx.x;
    if (e >= ne) return;
    int dv = max(vcnt[ev[e]], 1);
    int dc = max(ccnt[ec[e]], 1);
    inv[e] = 1.0f / (sqrtf((float)dv) * sqrtf((float)dc));
}

// ---------------- fused 2-layer MLP on tensor cores (mma.sync) ----------------
// grid: [2*vtiles + 2*ctiles] CTAs of 256 threads; 128-row tile each; 8 warps x 16 rows.
__global__ __launch_bounds__(256) void mlp_tc_kernel(
    const float* __restrict__ vt, const float* __restrict__ ct, int V, int C,
    const float* __restrict__ b1, const float* __restrict__ b2,
    int vtiles, int ctiles) {
    extern __shared__ char smem[];
    const uint32_t sA = smem_u32(smem);
    const uint32_t sAlo = sA + SM_ALO, sB = sA + SM_BHI, sBlo = sA + SM_BLO;

    int bx = blockIdx.x, seg, local;
    if (bx < vtiles)                   { seg = 0; local = bx; }
    else if (bx < 2 * vtiles)          { seg = 1; local = bx - vtiles; }
    else if (bx < 2 * vtiles + ctiles) { seg = 2; local = bx - 2 * vtiles; }
    else                               { seg = 3; local = bx - 2 * vtiles - ctiles; }

    const float* X = (seg < 2) ? vt : ct;
    const int N = (seg < 2) ? V : C;
    float* Y = g_msg + ((seg == 0) ? (size_t)0
                 : (seg == 1) ? (size_t)VMAX * DIM
                 : (seg == 2) ? (size_t)2 * VMAX * DIM
                              : ((size_t)2 * VMAX + CMAX) * DIM);
    const float* bb1 = b1 + seg * DIM;
    const float* bb2 = b2 + seg * DIM;

    const int tid = threadIdx.x;
    const int wid = tid >> 5;
    const int lid = tid & 31;
    const int mr = wid * 16;
    const int rowbase = local * 128;

    load_A(smem, X, rowbase, N, tid, 256);
    load_B(smem, seg, tid, 256);            // W1[seg]
    __syncthreads();

    float acc[16][4];
#pragma unroll
    for (int t = 0; t < 16; t++)
#pragma unroll
        for (int q = 0; q < 4; q++) acc[t][q] = 0.f;

    gemm3(sA, sAlo, sB, sBlo, acc, lid, mr);
    __syncthreads();                        // everyone done reading A & B

    // epilogue 1: H = relu(D + b1) -> split bf16 hi/lo straight back into A planes
    const int row0 = mr + (lid >> 2);
    const int c0l = (lid & 3) * 2;
#pragma unroll
    for (int nt = 0; nt < 16; nt++) {
        int col = nt * 8 + c0l;
        float2 bb = *reinterpret_cast<const float2*>(bb1 + col);
        float x0 = fmaxf(acc[nt][0] + bb.x, 0.f);
        float x1 = fmaxf(acc[nt][1] + bb.y, 0.f);
        float x2 = fmaxf(acc[nt][2] + bb.x, 0.f);
        float x3 = fmaxf(acc[nt][3] + bb.y, 0.f);
        float r0, r1, r2, r3;
        uint32_t oA = a_off(row0, col);
        uint32_t oB = a_off(row0 + 8, col);
        uint32_t h01 = pack_hi(x0, x1, r0, r1);
        uint32_t h23 = pack_hi(x2, x3, r2, r3);
        *reinterpret_cast<uint32_t*>(smem + SM_AHI + oA) = h01;
        *reinterpret_cast<uint32_t*>(smem + SM_ALO + oA) = pack_lo(r0, r1);
        *reinterpret_cast<uint32_t*>(smem + SM_AHI + oB) = h23;
        *reinterpret_cast<uint32_t*>(smem + SM_ALO + oB) = pack_lo(r2, r3);
#pragma unroll
        for (int q = 0; q < 4; q++) acc[nt][q] = 0.f;
    }
    load_B(smem, 4 + seg, tid, 256);        // W2[seg]
    __syncthreads();

    gemm3(sA, sAlo, sB, sBlo, acc, lid, mr);

    // epilogue 2: Y = D + b2, direct global store (lanes 0-3 cover 32B contiguous)
#pragma unroll
    for (int nt = 0; nt < 16; nt++) {
        int col = nt * 8 + c0l;
        float2 bb = *reinterpret_cast<const float2*>(bb2 + col);
        int g0 = rowbase + row0;
        int g1 = g0 + 8;
        if (g0 < N)
            *reinterpret_cast<float2*>(Y + (size_t)g0 * DIM + col) =
                make_float2(acc[nt][0] + bb.x, acc[nt][1] + bb.y);
        if (g1 < N)
            *reinterpret_cast<float2*>(Y + (size_t)g1 * DIM + col) =
                make_float2(acc[nt][2] + bb.x, acc[nt][3] + bb.y);
    }
}

// ---------------- update GEMM on tensor cores: Y = [X0|X1|X2] @ W(384x128) + b ----------
__global__ __launch_bounds__(256) void upd_tc_kernel(
    const float* __restrict__ X0, const float* __restrict__ X1, const float* __restrict__ X2,
    int N, int slot0, const float* __restrict__ b, float* __restrict__ Y) {
    extern __shared__ char smem[];
    const uint32_t sA = smem_u32(smem);
    const uint32_t sAlo = sA + SM_ALO, sB = sA + SM_BHI, sBlo = sA + SM_BLO;

    const int tid = threadIdx.x;
    const int wid = tid >> 5;
    const int lid = tid & 31;
    const int mr = wid * 16;
    const int rowbase = blockIdx.x * 128;

    float acc[16][4];
#pragma unroll
    for (int t = 0; t < 16; t++)
#pragma unroll
        for (int q = 0; q < 4; q++) acc[t][q] = 0.f;

    for (int s = 0; s < 3; s++) {
        const float* Xp = (s == 0) ? X0 : ((s == 1) ? X1 : X2);
        load_A(smem, Xp, rowbase, N, tid, 256);
        load_B(smem, slot0 + s, tid, 256);
        __syncthreads();
        gemm3(sA, sAlo, sB, sBlo, acc, lid, mr);
        __syncthreads();
    }

    const int row0 = mr + (lid >> 2);
    const int c0l = (lid & 3) * 2;
#pragma unroll
    for (int nt = 0; nt < 16; nt++) {
        int col = nt * 8 + c0l;
        float2 bb = *reinterpret_cast<const float2*>(b + col);
        int g0 = rowbase + row0;
        int g1 = g0 + 8;
        if (g0 < N)
            *reinterpret_cast<float2*>(Y + (size_t)g0 * DIM + col) =
                make_float2(acc[nt][0] + bb.x, acc[nt][1] + bb.y);
        if (g1 < N)
            *reinterpret_cast<float2*>(Y + (size_t)g1 * DIM + col) =
                make_float2(acc[nt][2] + bb.x, acc[nt][3] + bb.y);
    }
}

// ---------------- edge scatter: both directions, one pass, v4 reductions --------
__global__ void scatter_kernel(const int* __restrict__ ev, const int* __restrict__ ec,
                               const float* __restrict__ inv, int ne,
                               const float* __restrict__ msg_v, const float* __restrict__ msg_c,
                               float* __restrict__ agg_c, float* __restrict__ agg_v) {
    int idx = blockIdx.x * blockDim.x + threadIdx.x;
    if (idx >= ne * 32) return;
    int e = idx >> 5;
    int j = (idx & 31) * 4;
    int v = ev[e];
    int c = ec[e];
    float s = inv[e];

    float4 mv = *reinterpret_cast<const float4*>(msg_v + (size_t)v * DIM + j);
    float* dc = agg_c + (size_t)c * DIM + j;
    asm volatile("red.global.add.v4.f32 [%0], {%1, %2, %3, %4};"
                 :: "l"(dc), "f"(mv.x * s), "f"(mv.y * s), "f"(mv.z * s), "f"(mv.w * s)
                 : "memory");

    float4 mc = *reinterpret_cast<const float4*>(msg_c + (size_t)c * DIM + j);
    float* dv = agg_v + (size_t)v * DIM + j;
    asm volatile("red.global.add.v4.f32 [%0], {%1, %2, %3, %4};"
                 :: "l"(dv), "f"(mc.x * s), "f"(mc.y * s), "f"(mc.z * s), "f"(mc.w * s)
                 : "memory");
}

// ---------------- host launcher ----------------
extern "C" void kernel_launch(void* const* d_in, const int* in_sizes, int n_in,
                              void* d_out, int out_size) {
    int base = (in_sizes[0] == 1 && in_sizes[1] == 1) ? 2 : 0;
    const int*   v_edge = (const int*)d_in[base + 0];
    const int*   c_edge = (const int*)d_in[base + 1];
    const int*   p_idx  = (const int*)d_in[base + 2];
    const int*   n_idx  = (const int*)d_in[base + 3];
    const float* v_emb  = (const float*)d_in[base + 4];
    const float* c_emb  = (const float*)d_in[base + 5];
    const float* W1     = (const float*)d_in[base + 6];
    const float* b1     = (const float*)d_in[base + 7];
    const float* W2     = (const float*)d_in[base + 8];
    const float* b2     = (const float*)d_in[base + 9];
    const float* cW     = (const float*)d_in[base + 10];
    const float* cb     = (const float*)d_in[base + 11];
    const float* vW     = (const float*)d_in[base + 12];
    const float* vbias  = (const float*)d_in[base + 13];

    const int EP = in_sizes[base + 2];
    const int EN = in_sizes[base + 3];
    const int V  = in_sizes[base + 4] / DIM;
    const int C  = in_sizes[base + 5] / DIM;

    int *pv, *pc, *nv, *nc, *cnt;
    float *pinv, *ninv, *msg, *agg;
    cudaGetSymbolAddress((void**)&pv,   g_pv);
    cudaGetSymbolAddress((void**)&pc,   g_pc);
    cudaGetSymbolAddress((void**)&nv,   g_nv);
    cudaGetSymbolAddress((void**)&nc,   g_nc);
    cudaGetSymbolAddress((void**)&pinv, g_pinv);
    cudaGetSymbolAddress((void**)&ninv, g_ninv);
    cudaGetSymbolAddress((void**)&cnt,  g_cnt);
    cudaGetSymbolAddress((void**)&msg,  g_msg);
    cudaGetSymbolAddress((void**)&agg,  g_agg);

    int* vcnt_p = cnt;
    int* vcnt_n = cnt + VMAX;
    int* ccnt_p = cnt + 2 * VMAX;
    int* ccnt_n = cnt + 2 * VMAX + CMAX;
    float* mv_p = msg;
    float* mv_n = msg + (size_t)VMAX * DIM;
    float* mc_p = msg + (size_t)2 * VMAX * DIM;
    float* mc_n = msg + ((size_t)2 * VMAX + CMAX) * DIM;
    float* vagg_p = agg;
    float* vagg_n = agg + (size_t)VMAX * DIM;
    float* cagg_p = agg + (size_t)2 * VMAX * DIM;
    float* cagg_n = agg + ((size_t)2 * VMAX + CMAX) * DIM;

    cudaFuncSetAttribute(mlp_tc_kernel, cudaFuncAttributeMaxDynamicSharedMemorySize, SM_BYTES);
    cudaFuncSetAttribute(upd_tc_kernel, cudaFuncAttributeMaxDynamicSharedMemorySize, SM_BYTES);

    // one-time per launch: weight split/transpose/block + degree norms
    prep_kernel<<<(14 * 16384 + 255) / 256, 256>>>(W1, W2, cW, vW);
    cudaMemsetAsync(cnt, 0, (size_t)(2 * VMAX + 2 * CMAX) * sizeof(int));
    count_kernel<<<(EP + 255) / 256, 256>>>(p_idx, v_edge, c_edge, EP, vcnt_p, ccnt_p, pv, pc);
    count_kernel<<<(EN + 255) / 256, 256>>>(n_idx, v_edge, c_edge, EN, vcnt_n, ccnt_n, nv, nc);
    inv_kernel<<<(EP + 255) / 256, 256>>>(pv, pc, vcnt_p, ccnt_p, EP, pinv);
    inv_kernel<<<(EN + 255) / 256, 256>>>(nv, nc, vcnt_n, ccnt_n, EN, ninv);

    // output slab doubles as the embedding history: [5,V,128] then [5,C,128]
    float* out   = (float*)d_out;
    float* out_v = out;
    float* out_c = out + (size_t)(NITER + 1) * V * DIM;
    cudaMemcpyAsync(out_v, v_emb, (size_t)V * DIM * sizeof(float), cudaMemcpyDeviceToDevice);
    cudaMemcpyAsync(out_c, c_emb, (size_t)C * DIM * sizeof(float), cudaMemcpyDeviceToDevice);

    const int vtiles = (V + 127) / 128;
    const int ctiles = (C + 127) / 128;
    const int mlpblocks = 2 * vtiles + 2 * ctiles;
    const size_t aggBytes = (size_t)(2 * VMAX + 2 * CMAX) * DIM * sizeof(float);

    for (int t = 0; t < NITER; t++) {
        const float* vt = out_v + (size_t)t * V * DIM;
        const float* ct = out_c + (size_t)t * C * DIM;

        mlp_tc_kernel<<<mlpblocks, 256, SM_BYTES>>>(vt, ct, V, C, b1, b2, vtiles, ctiles);

        cudaMemsetAsync(agg, 0, aggBytes);
        scatter_kernel<<<(EP * 32 + 255) / 256, 256>>>(pv, pc, pinv, EP, mv_p, mc_p, cagg_p, vagg_p);
        scatter_kernel<<<(EN * 32 + 255) / 256, 256>>>(nv, nc, ninv, EN, mv_n, mc_n, cagg_n, vagg_n);

        upd_tc_kernel<<<ctiles, 256, SM_BYTES>>>(ct, cagg_p, cagg_n, C, 8, cb,
                                                 out_c + (size_t)(t + 1) * C * DIM);
        upd_tc_kernel<<<vtiles, 256, SM_BYTES>>>(vt, vagg_p, vagg_n, V, 11, vbias,
                                                 out_v + (size_t)(t + 1) * V * DIM);
    }
}

// round 12
// speedup vs baseline: 2.9180x; 1.2382x over previous
#include <cuda_runtime.h>
#include <cuda_bf16.h>
#include <cstdint>

#define DIM 128
#define VMAX 50000
#define CMAX 150000
#define EPMAX 200000
#define ENMAX 200000
#define NITER 4
#define NCNT (2 * VMAX + 2 * CMAX)          // 400000
#define SCAN_NBLK ((NCNT + 1023) / 1024)    // 391

// ---------------- static device scratch (no allocations allowed) ----------------
__device__ int   g_pv[EPMAX];
__device__ int   g_pc[EPMAX];
__device__ int   g_nv[ENMAX];
__device__ int   g_nc[ENMAX];
// counts: [vp (VMAX) | vn (VMAX) | cp (CMAX) | cn (CMAX)]
__device__ int   g_cnt[NCNT];
__device__ int   g_off[NCNT];
__device__ int   g_cursor[NCNT];
__device__ int   g_bsum[SCAN_NBLK];
__device__ int   g_csr[2 * EPMAX + 2 * ENMAX];
// msg layout: [mv_p (V*128) | mv_n (V*128) | mc_p (C*128) | mc_n (C*128)] (pre-scaled by rsqrt(src deg))
__device__ float g_msg[(size_t)NCNT * DIM];
// agg layout: [vagg_p | vagg_n | cagg_p | cagg_n]
__device__ float g_agg[(size_t)NCNT * DIM];
// pre-split bf16 weight images, B-operand layout [N][K], blocked 8x8 atoms.
// slots: 0-3 W1[seg], 4-7 W2[seg], 8-10 cW parts, 11-13 vW parts. per slot: hi 32KB then lo 32KB.
__device__ unsigned char g_wb[14 * 65536];

// ---------------- helpers ----------------
__device__ __forceinline__ uint32_t smem_u32(const void* p) {
    uint32_t a;
    asm("{ .reg .u64 t; cvta.to.shared.u64 t, %1; cvt.u32.u64 %0, t; }" : "=r"(a) : "l"(p));
    return a;
}

// blocked 8x8 bf16 atom layout for a [128][128] tile: atom = 8 rows x 8 cols = 128B contiguous.
__device__ __forceinline__ uint32_t a_off(int row, int col) {
    return (uint32_t)(((row >> 3) * 16 + (col >> 3)) * 128 + (row & 7) * 16 + (col & 7) * 2);
}

__device__ __forceinline__ void ldsm4(uint32_t* r, uint32_t addr) {
    asm volatile("ldmatrix.sync.aligned.m8n8.x4.shared.b16 {%0,%1,%2,%3}, [%4];"
                 : "=r"(r[0]), "=r"(r[1]), "=r"(r[2]), "=r"(r[3]) : "r"(addr));
}

__device__ __forceinline__ void mma16816(float* c, const uint32_t* a, const uint32_t* b) {
    asm volatile(
        "mma.sync.aligned.m16n8k16.row.col.f32.bf16.bf16.f32 "
        "{%0,%1,%2,%3}, {%4,%5,%6,%7}, {%8,%9}, {%0,%1,%2,%3};"
        : "+f"(c[0]), "+f"(c[1]), "+f"(c[2]), "+f"(c[3])
        : "r"(a[0]), "r"(a[1]), "r"(a[2]), "r"(a[3]), "r"(b[0]), "r"(b[1]));
}

__device__ __forceinline__ uint32_t pack_hi(float x0, float x1, float& r0, float& r1) {
    __nv_bfloat16 h0 = __float2bfloat16(x0), h1 = __float2bfloat16(x1);
    r0 = x0 - __bfloat162float(h0);
    r1 = x1 - __bfloat162float(h1);
    return (uint32_t)__bfloat16_as_ushort(h0) | ((uint32_t)__bfloat16_as_ushort(h1) << 16);
}
__device__ __forceinline__ uint32_t pack_lo(float r0, float r1) {
    __nv_bfloat16 l0 = __float2bfloat16(r0), l1 = __float2bfloat16(r1);
    return (uint32_t)__bfloat16_as_ushort(l0) | ((uint32_t)__bfloat16_as_ushort(l1) << 16);
}

// smem plane offsets (A = X tile, H = hidden tile, B = weights), each plane 32KB
#define SM_AHI 0
#define SM_ALO 32768
#define SM_HHI 65536
#define SM_HLO 98304
#define SM_BHI 131072
#define SM_BLO 163840
#define SM_MLP_BYTES 196608
#define SM_UPD_BYTES 196608

// load 128-row X tile (fp32 global) -> split bf16 hi/lo into blocked smem A planes
__device__ __forceinline__ void load_A(char* smem, const float* __restrict__ X,
                                       int rowbase, int N, int tid, int nthr) {
    for (int i = tid; i < 128 * 32; i += nthr) {
        int row = i >> 5;
        int cg = (i & 31) * 4;
        float4 x = make_float4(0.f, 0.f, 0.f, 0.f);
        int grow = rowbase + row;
        if (grow < N) x = *reinterpret_cast<const float4*>(X + (size_t)grow * DIM + cg);
        float rx, ry, rz, rw;
        uint32_t h01 = pack_hi(x.x, x.y, rx, ry);
        uint32_t h23 = pack_hi(x.z, x.w, rz, rw);
        uint32_t l01 = pack_lo(rx, ry);
        uint32_t l23 = pack_lo(rz, rw);
        uint32_t o = a_off(row, cg);
        *reinterpret_cast<uint2*>(smem + SM_AHI + o) = make_uint2(h01, h23);
        *reinterpret_cast<uint2*>(smem + SM_ALO + o) = make_uint2(l01, l23);
    }
}

// copy one pre-built 64KB weight image (hi 32KB + lo 32KB) into smem B planes
__device__ __forceinline__ void load_B(char* smem, int slot, int tid, int nthr) {
    const float4* src = reinterpret_cast<const float4*>(g_wb + (size_t)slot * 65536);
    float4* dst = reinterpret_cast<float4*>(smem + SM_BHI);
    for (int i = tid; i < 4096; i += nthr) dst[i] = src[i];
}

// 128x128x128 GEMM, 3-term bf16 split, accumulate into acc[16][4] (warp = 16 rows).
__device__ __forceinline__ void gemm3(uint32_t sA, uint32_t sAlo, uint32_t sB, uint32_t sBlo,
                                      float acc[16][4], int lid, int mr) {
    const int j = lid >> 3, lr = lid & 7;
    const uint32_t ac = (uint32_t)(((mr >> 3) + (j & 1)) * 16 + (j >> 1)) * 128 + lr * 16;
    const uint32_t bc = (uint32_t)((j >> 1) * 16 + (j & 1)) * 128 + lr * 16;
#pragma unroll
    for (int ks = 0; ks < 8; ks++) {
        uint32_t ah[4], al[4];
        ldsm4(ah, sA + ac + ks * 256);
        ldsm4(al, sAlo + ac + ks * 256);
#pragma unroll
        for (int p = 0; p < 8; p++) {
            uint32_t bh[4], bl[4];
            ldsm4(bh, sB + bc + p * 4096 + ks * 256);
            ldsm4(bl, sBlo + bc + p * 4096 + ks * 256);
            mma16816(acc[2 * p],     ah, bh);
            mma16816(acc[2 * p + 1], ah, bh + 2);
            mma16816(acc[2 * p],     al, bh);
            mma16816(acc[2 * p + 1], al, bh + 2);
            mma16816(acc[2 * p],     ah, bl);
            mma16816(acc[2 * p + 1], ah, bl + 2);
        }
    }
}

// ---------------- weight prep: split + transpose + block, once per launch ----------------
__global__ void prep_kernel(const float* __restrict__ W1, const float* __restrict__ W2,
                            const float* __restrict__ cW, const float* __restrict__ vW) {
    int idx = blockIdx.x * blockDim.x + threadIdx.x;
    if (idx >= 14 * 16384) return;
    int slot = idx >> 14;
    int e = idx & 16383;
    int n = e >> 7;     // B row (output col)
    int k = e & 127;    // B col (reduction)
    float w;
    if (slot < 4)       w = W1[(size_t)slot * 16384 + k * 128 + n];
    else if (slot < 8)  w = W2[(size_t)(slot - 4) * 16384 + k * 128 + n];
    else if (slot < 11) w = cW[(size_t)((slot - 8) * 128 + k) * 128 + n];
    else                w = vW[(size_t)((slot - 11) * 128 + k) * 128 + n];
    __nv_bfloat16 h = __float2bfloat16(w);
    __nv_bfloat16 l = __float2bfloat16(w - __bfloat162float(h));
    unsigned char* base = g_wb + (size_t)slot * 65536;
    uint32_t o = a_off(n, k);
    *reinterpret_cast<__nv_bfloat16*>(base + o) = h;
    *reinterpret_cast<__nv_bfloat16*>(base + 32768 + o) = l;
}

// ---------------- CSR build ----------------
__global__ void count_kernel(const int* __restrict__ eidx,
                             const int* __restrict__ vI, const int* __restrict__ cI,
                             int ne, int vbase, int cbase,
                             int* __restrict__ ev, int* __restrict__ ec) {
    int e = blockIdx.x * blockDim.x + threadIdx.x;
    if (e >= ne) return;
    int ed = eidx[e];
    int v = vI[ed];
    int c = cI[ed];
    ev[e] = v; ec[e] = c;
    atomicAdd(g_cnt + vbase + v, 1);
    atomicAdd(g_cnt + cbase + c, 1);
}

// exclusive scan over g_cnt (1024 elems / block of 256 threads)
__global__ __launch_bounds__(256) void scan1_kernel() {
    __shared__ int wsum[8];
    int b = blockIdx.x, t = threadIdx.x;
    int base = b * 1024 + t * 4;
    int v[4];
#pragma unroll
    for (int i = 0; i < 4; i++) v[i] = (base + i < NCNT) ? g_cnt[base + i] : 0;
    int ts = v[0] + v[1] + v[2] + v[3];
    int lane = t & 31, wid = t >> 5;
    int inc = ts;
#pragma unroll
    for (int d = 1; d < 32; d <<= 1) { int n = __shfl_up_sync(~0u, inc, d); if (lane >= d) inc += n; }
    if (lane == 31) wsum[wid] = inc;
    __syncthreads();
    if (wid == 0) {
        int s = (lane < 8) ? wsum[lane] : 0;
#pragma unroll
        for (int d = 1; d < 8; d <<= 1) { int n = __shfl_up_sync(~0u, s, d); if (lane >= d) s += n; }
        if (lane < 8) wsum[lane] = s;   // inclusive warp sums
    }
    __syncthreads();
    int woff = (wid == 0) ? 0 : wsum[wid - 1];
    int run = woff + inc - ts;   // exclusive offset for this thread
#pragma unroll
    for (int i = 0; i < 4; i++) { if (base + i < NCNT) g_off[base + i] = run; run += v[i]; }
    if (t == 255) g_bsum[b] = run;   // block total
}

__global__ __launch_bounds__(512) void scan2_kernel() {
    __shared__ int ws[16];
    int t = threadIdx.x;
    int v = (t < SCAN_NBLK) ? g_bsum[t] : 0;
    int lane = t & 31, wid = t >> 5;
    int inc = v;
#pragma unroll
    for (int d = 1; d < 32; d <<= 1) { int n = __shfl_up_sync(~0u, inc, d); if (lane >= d) inc += n; }
    if (lane == 31) ws[wid] = inc;
    __syncthreads();
    if (wid == 0) {
        int s = (lane < 16) ? ws[lane] : 0;
#pragma unroll
        for (int d = 1; d < 16; d <<= 1) { int n = __shfl_up_sync(~0u, s, d); if (lane >= d) s += n; }
        if (lane < 16) ws[lane] = s;
    }
    __syncthreads();
    int woff = (wid == 0) ? 0 : ws[wid - 1];
    if (t < SCAN_NBLK) g_bsum[t] = woff + inc - v;   // exclusive
}

__global__ void scan3_kernel() {
    int i = blockIdx.x * blockDim.x + threadIdx.x;
    if (i >= NCNT) return;
    int o = g_off[i] + g_bsum[i >> 10];
    g_off[i] = o;
    g_cursor[i] = o;
}

__global__ void fill_kernel(const int* __restrict__ ev, const int* __restrict__ ec,
                            int ne, int vbase, int cbase) {
    int e = blockIdx.x * blockDim.x + threadIdx.x;
    if (e >= ne) return;
    int v = ev[e], c = ec[e];
    int p1 = atomicAdd(g_cursor + vbase + v, 1);
    g_csr[p1] = c;                                  // var's incident clause (c2v source)
    int p2 = atomicAdd(g_cursor + cbase + c, 1);
    g_csr[p2] = v;                                  // clause's incident var (v2c source)
}

// ---------------- CSR aggregation: one warp per destination node ----------------
__global__ __launch_bounds__(256) void agg_kernel() {
    int gw = (blockIdx.x * 256 + threadIdx.x) >> 5;
    int lane = threadIdx.x & 31;
    if (gw >= NCNT) return;

    const float* slab;
    float* outp;
    int row;
    if (gw < VMAX)                 { slab = g_msg + (size_t)2 * VMAX * DIM;               outp = g_agg;                                       row = gw; }
    else if (gw < 2 * VMAX)        { slab = g_msg + ((size_t)2 * VMAX + CMAX) * DIM;       outp = g_agg + (size_t)VMAX * DIM;                  row = gw - VMAX; }
    else if (gw < 2 * VMAX + CMAX) { slab = g_msg;                                         outp = g_agg + (size_t)2 * VMAX * DIM;              row = gw - 2 * VMAX; }
    else                           { slab = g_msg + (size_t)VMAX * DIM;                    outp = g_agg + ((size_t)2 * VMAX + CMAX) * DIM;     row = gw - 2 * VMAX - CMAX; }

    int deg = g_cnt[gw];
    int off = g_off[gw];
    float4 acc = make_float4(0.f, 0.f, 0.f, 0.f);
    for (int j = 0; j < deg; j++) {
        int s = g_csr[off + j];
        float4 m = *reinterpret_cast<const float4*>(slab + (size_t)s * DIM + lane * 4);
        acc.x += m.x; acc.y += m.y; acc.z += m.z; acc.w += m.w;
    }
    float sc = rsqrtf((float)max(deg, 1));
    acc.x *= sc; acc.y *= sc; acc.z *= sc; acc.w *= sc;
    *reinterpret_cast<float4*>(outp + (size_t)row * DIM + lane * 4) = acc;
}

// ---------------- fused 2-layer MLP, both polarities per tile ----------------
// grid: [vtiles + ctiles] CTAs of 256 threads; 128-row tile; 8 warps x 16 rows.
__global__ __launch_bounds__(256) void mlp_tc_kernel(
    const float* __restrict__ vt, const float* __restrict__ ct, int V, int C,
    const float* __restrict__ b1, const float* __restrict__ b2, int vtiles) {
    extern __shared__ char smem[];
    const uint32_t sb = smem_u32(smem);

    const int bx = blockIdx.x;
    const bool isv = (bx < vtiles);
    const int local = isv ? bx : bx - vtiles;
    const float* X = isv ? vt : ct;
    const int N = isv ? V : C;

    const int tid = threadIdx.x;
    const int wid = tid >> 5;
    const int lid = tid & 31;
    const int mr = wid * 16;
    const int rowbase = local * 128;
    const int row0 = mr + (lid >> 2);
    const int c0l = (lid & 3) * 2;
    const int g0 = rowbase + row0;
    const int g1 = g0 + 8;

    load_A(smem, X, rowbase, N, tid, 256);

    float acc[16][4];
#pragma unroll
    for (int pol = 0; pol < 2; pol++) {
        const int seg = (isv ? 0 : 2) + pol;
        const float* bb1 = b1 + seg * DIM;
        const float* bb2 = b2 + seg * DIM;
        float* Y = g_msg + ((seg == 0) ? (size_t)0
                     : (seg == 1) ? (size_t)VMAX * DIM
                     : (seg == 2) ? (size_t)2 * VMAX * DIM
                                  : ((size_t)2 * VMAX + CMAX) * DIM);
        const int cntbase = (seg == 0) ? 0 : (seg == 1) ? VMAX
                          : (seg == 2) ? 2 * VMAX : 2 * VMAX + CMAX;

        __syncthreads();                       // prior readers of B (and first-iter A load)
        load_B(smem, seg, tid, 256);           // W1[seg]
        __syncthreads();

#pragma unroll
        for (int t = 0; t < 16; t++)
#pragma unroll
            for (int q = 0; q < 4; q++) acc[t][q] = 0.f;
        gemm3(sb + SM_AHI, sb + SM_ALO, sb + SM_BHI, sb + SM_BLO, acc, lid, mr);

        // epilogue 1: H = relu(D + b1) -> split bf16 hi/lo into H planes
#pragma unroll
        for (int nt = 0; nt < 16; nt++) {
            int col = nt * 8 + c0l;
            float2 bb = *reinterpret_cast<const float2*>(bb1 + col);
            float x0 = fmaxf(acc[nt][0] + bb.x, 0.f);
            float x1 = fmaxf(acc[nt][1] + bb.y, 0.f);
            float x2 = fmaxf(acc[nt][2] + bb.x, 0.f);
            float x3 = fmaxf(acc[nt][3] + bb.y, 0.f);
            float r0, r1, r2, r3;
            uint32_t oA = a_off(row0, col);
            uint32_t oB = a_off(row0 + 8, col);
            uint32_t h01 = pack_hi(x0, x1, r0, r1);
            uint32_t h23 = pack_hi(x2, x3, r2, r3);
            *reinterpret_cast<uint32_t*>(smem + SM_HHI + oA) = h01;
            *reinterpret_cast<uint32_t*>(smem + SM_HLO + oA) = pack_lo(r0, r1);
            *reinterpret_cast<uint32_t*>(smem + SM_HHI + oB) = h23;
            *reinterpret_cast<uint32_t*>(smem + SM_HLO + oB) = pack_lo(r2, r3);
#pragma unroll
            for (int q = 0; q < 4; q++) acc[nt][q] = 0.f;
        }
        __syncthreads();                       // H complete; B readers done
        load_B(smem, 4 + seg, tid, 256);       // W2[seg]
        __syncthreads();

        gemm3(sb + SM_HHI, sb + SM_HLO, sb + SM_BHI, sb + SM_BLO, acc, lid, mr);

        // epilogue 2: Y = (D + b2) * rsqrt(src deg), direct global store
        float s0 = 0.f, s1 = 0.f;
        if (g0 < N) s0 = rsqrtf((float)max(g_cnt[cntbase + g0], 1));
        if (g1 < N) s1 = rsqrtf((float)max(g_cnt[cntbase + g1], 1));
#pragma unroll
        for (int nt = 0; nt < 16; nt++) {
            int col = nt * 8 + c0l;
            float2 bb = *reinterpret_cast<const float2*>(bb2 + col);
            if (g0 < N)
                *reinterpret_cast<float2*>(Y + (size_t)g0 * DIM + col) =
                    make_float2((acc[nt][0] + bb.x) * s0, (acc[nt][1] + bb.y) * s0);
            if (g1 < N)
                *reinterpret_cast<float2*>(Y + (size_t)g1 * DIM + col) =
                    make_float2((acc[nt][2] + bb.x) * s1, (acc[nt][3] + bb.y) * s1);
        }
    }
}

// ---------------- update GEMM on tensor cores: Y = [X0|X1|X2] @ W(384x128) + b ----------
__global__ __launch_bounds__(256) void upd_tc_kernel(
    const float* __restrict__ X0, const float* __restrict__ X1, const float* __restrict__ X2,
    int N, int slot0, const float* __restrict__ b, float* __restrict__ Y) {
    extern __shared__ char smem[];
    const uint32_t sb = smem_u32(smem);

    const int tid = threadIdx.x;
    const int wid = tid >> 5;
    const int lid = tid & 31;
    const int mr = wid * 16;
    const int rowbase = blockIdx.x * 128;

    float acc[16][4];
#pragma unroll
    for (int t = 0; t < 16; t++)
#pragma unroll
        for (int q = 0; q < 4; q++) acc[t][q] = 0.f;

    for (int s = 0; s < 3; s++) {
        const float* Xp = (s == 0) ? X0 : ((s == 1) ? X1 : X2);
        load_A(smem, Xp, rowbase, N, tid, 256);
        load_B(smem, slot0 + s, tid, 256);
        __syncthreads();
        gemm3(sb + SM_AHI, sb + SM_ALO, sb + SM_BHI, sb + SM_BLO, acc, lid, mr);
        __syncthreads();
    }

    const int row0 = mr + (lid >> 2);
    const int c0l = (lid & 3) * 2;
#pragma unroll
    for (int nt = 0; nt < 16; nt++) {
        int col = nt * 8 + c0l;
        float2 bb = *reinterpret_cast<const float2*>(b + col);
        int g0 = rowbase + row0;
        int g1 = g0 + 8;
        if (g0 < N)
            *reinterpret_cast<float2*>(Y + (size_t)g0 * DIM + col) =
                make_float2(acc[nt][0] + bb.x, acc[nt][1] + bb.y);
        if (g1 < N)
            *reinterpret_cast<float2*>(Y + (size_t)g1 * DIM + col) =
                make_float2(acc[nt][2] + bb.x, acc[nt][3] + bb.y);
    }
}

// ---------------- host launcher ----------------
extern "C" void kernel_launch(void* const* d_in, const int* in_sizes, int n_in,
                              void* d_out, int out_size) {
    int base = (in_sizes[0] == 1 && in_sizes[1] == 1) ? 2 : 0;
    const int*   v_edge = (const int*)d_in[base + 0];
    const int*   c_edge = (const int*)d_in[base + 1];
    const int*   p_idx  = (const int*)d_in[base + 2];
    const int*   n_idx  = (const int*)d_in[base + 3];
    const float* v_emb  = (const float*)d_in[base + 4];
    const float* c_emb  = (const float*)d_in[base + 5];
    const float* W1     = (const float*)d_in[base + 6];
    const float* b1     = (const float*)d_in[base + 7];
    const float* W2     = (const float*)d_in[base + 8];
    const float* b2     = (const float*)d_in[base + 9];
    const float* cW     = (const float*)d_in[base + 10];
    const float* cb     = (const float*)d_in[base + 11];
    const float* vW     = (const float*)d_in[base + 12];
    const float* vbias  = (const float*)d_in[base + 13];

    const int EP = in_sizes[base + 2];
    const int EN = in_sizes[base + 3];
    const int V  = in_sizes[base + 4] / DIM;
    const int C  = in_sizes[base + 5] / DIM;

    int *pv, *pc, *nv, *nc, *cnt;
    float *msg, *agg;
    cudaGetSymbolAddress((void**)&pv,  g_pv);
    cudaGetSymbolAddress((void**)&pc,  g_pc);
    cudaGetSymbolAddress((void**)&nv,  g_nv);
    cudaGetSymbolAddress((void**)&nc,  g_nc);
    cudaGetSymbolAddress((void**)&cnt, g_cnt);
    cudaGetSymbolAddress((void**)&msg, g_msg);
    cudaGetSymbolAddress((void**)&agg, g_agg);

    float* vagg_p = agg;
    float* vagg_n = agg + (size_t)VMAX * DIM;
    float* cagg_p = agg + (size_t)2 * VMAX * DIM;
    float* cagg_n = agg + ((size_t)2 * VMAX + CMAX) * DIM;

    cudaFuncSetAttribute(mlp_tc_kernel, cudaFuncAttributeMaxDynamicSharedMemorySize, SM_MLP_BYTES);
    cudaFuncSetAttribute(upd_tc_kernel, cudaFuncAttributeMaxDynamicSharedMemorySize, SM_UPD_BYTES);

    // one-time per call: weight prep + CSR build
    prep_kernel<<<(14 * 16384 + 255) / 256, 256>>>(W1, W2, cW, vW);
    cudaMemsetAsync(cnt, 0, (size_t)NCNT * sizeof(int));
    count_kernel<<<(EP + 255) / 256, 256>>>(p_idx, v_edge, c_edge, EP, 0, 2 * VMAX, pv, pc);
    count_kernel<<<(EN + 255) / 256, 256>>>(n_idx, v_edge, c_edge, EN, VMAX, 2 * VMAX + CMAX, nv, nc);
    scan1_kernel<<<SCAN_NBLK, 256>>>();
    scan2_kernel<<<1, 512>>>();
    scan3_kernel<<<(NCNT + 255) / 256, 256>>>();
    fill_kernel<<<(EP + 255) / 256, 256>>>(pv, pc, EP, 0, 2 * VMAX);
    fill_kernel<<<(EN + 255) / 256, 256>>>(nv, nc, EN, VMAX, 2 * VMAX + CMAX);

    // output slab doubles as the embedding history: [5,V,128] then [5,C,128]
    float* out   = (float*)d_out;
    float* out_v = out;
    float* out_c = out + (size_t)(NITER + 1) * V * DIM;
    cudaMemcpyAsync(out_v, v_emb, (size_t)V * DIM * sizeof(float), cudaMemcpyDeviceToDevice);
    cudaMemcpyAsync(out_c, c_emb, (size_t)C * DIM * sizeof(float), cudaMemcpyDeviceToDevice);

    const int vtiles = (V + 127) / 128;
    const int ctiles = (C + 127) / 128;
    const int aggblocks = (NCNT * 32 + 255) / 256;

    for (int t = 0; t < NITER; t++) {
        const float* vt = out_v + (size_t)t * V * DIM;
        const float* ct = out_c + (size_t)t * C * DIM;

        // 4 message MLPs (both polarities fused per tile), outputs pre-scaled by rsqrt(src deg)
        mlp_tc_kernel<<<vtiles + ctiles, 256, SM_MLP_BYTES>>>(vt, ct, V, C, b1, b2, vtiles);

        // CSR gather-reduce aggregation (no atomics, no memset), scaled by rsqrt(dest deg)
        agg_kernel<<<aggblocks, 256>>>();

        // node updates (concat GEMM, K=384)
        upd_tc_kernel<<<ctiles, 256, SM_UPD_BYTES>>>(ct, cagg_p, cagg_n, C, 8, cb,
                                                     out_c + (size_t)(t + 1) * C * DIM);
        upd_tc_kernel<<<vtiles, 256, SM_UPD_BYTES>>>(vt, vagg_p, vagg_n, V, 11, vbias,
                                                     out_v + (size_t)(t + 1) * V * DIM);
    }
}